// round 15
// baseline (speedup 1.0000x reference)
#include <cuda_runtime.h>
#include <cuda_fp16.h>

#define BH_  32
#define H_   16
#define L_   4096
#define D_   128
#define CH_  128
#define NC_  32
#define NS_  (NC_ + 1)
#define EPS_ 1e-6f

// scratch: per-chunk state sums -> exclusive prefix (fp16), Z in fp32
__device__ __half g_S[(size_t)BH_ * NS_ * D_ * D_];
__device__ float  g_Z[(size_t)BH_ * NS_ * D_];

__device__ __forceinline__ unsigned su32(const void* p) {
  return (unsigned)__cvta_generic_to_shared(p);
}
__device__ __forceinline__ void cpasync16(unsigned dst, const void* src) {
  asm volatile("cp.async.cg.shared.global [%0], [%1], 16;\n" :: "r"(dst), "l"(src));
}
__device__ __forceinline__ void cpcommit() {
  asm volatile("cp.async.commit_group;\n");
}
template<int N> __device__ __forceinline__ void cp_wait() {
  asm volatile("cp.async.wait_group %0;\n" :: "n"(N));
}
__device__ __forceinline__ void ldsm4(unsigned& r0, unsigned& r1, unsigned& r2, unsigned& r3, unsigned a) {
  asm volatile("ldmatrix.sync.aligned.m8n8.x4.shared.b16 {%0,%1,%2,%3},[%4];"
               : "=r"(r0), "=r"(r1), "=r"(r2), "=r"(r3) : "r"(a));
}
__device__ __forceinline__ void ldsm4t(unsigned& r0, unsigned& r1, unsigned& r2, unsigned& r3, unsigned a) {
  asm volatile("ldmatrix.sync.aligned.m8n8.x4.trans.shared.b16 {%0,%1,%2,%3},[%4];"
               : "=r"(r0), "=r"(r1), "=r"(r2), "=r"(r3) : "r"(a));
}
__device__ __forceinline__ void mma16816(float c[4],
    unsigned a0, unsigned a1, unsigned a2, unsigned a3,
    unsigned b0, unsigned b1) {
  asm volatile(
    "mma.sync.aligned.m16n8k16.row.col.f32.f16.f16.f32 "
    "{%0,%1,%2,%3},{%4,%5,%6,%7},{%8,%9},{%0,%1,%2,%3};\n"
    : "+f"(c[0]), "+f"(c[1]), "+f"(c[2]), "+f"(c[3])
    : "r"(a0), "r"(a1), "r"(a2), "r"(a3), "r"(b0), "r"(b1));
}

__device__ __forceinline__ float phi_f(float x, float s, float b) {
  float y = fmaf(x, s, b);
  float p = (y > 0.f) ? (y + 1.f) : __expf(y);
  return fminf(p, 10.f);
}

// Swizzled fp16 tiles: row stride 128 halves; off(r,c) = r*128 + (((c>>3)^(r&7))<<3) + (c&7)

// ---------------------------------------------------------------------------
// pass1: S_c = phi_k^T V (fp16), Z_c = colsum(phi_k)
// R14 config + DEFERRED MMA: iteration tt stages pieces 4tt..4tt+3 and runs
// the mma for slices 2tt-2, 2tt-1 (staged last iteration) INTERLEAVED with
// the fill, before the barrier. Tail mma (slices 6,7) after the loop.
// smem: s_k[32KB] s_v[32KB] zones[6x8KB] z[512B] = 115200B
// ---------------------------------------------------------------------------
extern "C" __global__ void __launch_bounds__(256, 2)
la_pass1(const float* __restrict__ K, const float* __restrict__ V,
         const float* __restrict__ scale, const float* __restrict__ bias) {
  int c = blockIdx.x, bh = blockIdx.y, h = bh & (H_ - 1);
  extern __shared__ char smem[];
  __half* s_k = (__half*)smem;                 // 32768 B, swizzled 128x128
  __half* s_v = s_k + 128 * 128;               // +32768 B
  char*   zoneB = smem + 65536;                // 6 x 8192 B raw fp32
  float*  s_z  = (float*)(smem + 114688);      // 128 floats
  unsigned sb = su32(smem);
  int tid = threadIdx.x, lane = tid & 31;
  size_t off = ((size_t)bh * L_ + (size_t)c * CH_) * D_;

  // piece p: even -> K row-block p/2 ; odd -> V row-block p/2
  auto issue = [&](int p) {
    int t = p >> 1;
    const float* src = ((p & 1) == 0) ? (K + off + (size_t)t * 2048)
                                      : (V + off + (size_t)t * 2048);
    unsigned zb = sb + 65536u + (unsigned)(p % 6) * 8192u;
    cpasync16(zb + tid * 16, src + tid * 4);
    cpasync16(zb + (tid + 256) * 16, src + (tid + 256) * 4);
    cpcommit();
  };
  issue(0); issue(1); issue(2); issue(3); issue(4); issue(5);

  int colf = (tid & 31) * 4;
  float4 scv = *(const float4*)(scale + h * D_ + colf);
  float4 biv = *(const float4*)(bias  + h * D_ + colf);
  if (tid < 128) s_z[tid] = 0.f;
  float z0 = 0.f, z1 = 0.f, z2 = 0.f, z3 = 0.f;

  // mma frag setup (m32 x n64 warp tile)
  int w = tid >> 5, g = lane >> 2, t4 = lane & 3;
  int wm = w & 3, wn = w >> 2;
  int m0 = wm << 5, n0 = wn << 6;
  int l7 = lane & 7, ca3 = (lane >> 3) & 1, cb3 = lane >> 4;
  int rA = l7 + 8 * cb3;
  int rB = l7 + 8 * ca3;
  unsigned aB0 = sb + (unsigned)(rA * 256 + (((4 * wm + ca3) ^ l7) << 4));
  unsigned aB1 = sb + (unsigned)(rA * 256 + (((4 * wm + 2 + ca3) ^ l7) << 4));
  unsigned bB0 = sb + 32768u + (unsigned)(rB * 256 + (((8 * wn + cb3) ^ l7) << 4));
  unsigned bB1 = sb + 32768u + (unsigned)(rB * 256 + (((8 * wn + 2 + cb3) ^ l7) << 4));
  unsigned bB2 = sb + 32768u + (unsigned)(rB * 256 + (((8 * wn + 4 + cb3) ^ l7) << 4));
  unsigned bB3 = sb + 32768u + (unsigned)(rB * 256 + (((8 * wn + 6 + cb3) ^ l7) << 4));

  float acc[16][4];
#pragma unroll
  for (int jt = 0; jt < 16; jt++) { acc[jt][0] = acc[jt][1] = acc[jt][2] = acc[jt][3] = 0.f; }

  auto mma_slice = [&](int s) {
    unsigned ko = (unsigned)(s * 16 * 256);
    unsigned a00, a01, a02, a03, a10, a11, a12, a13;
    ldsm4t(a00, a01, a02, a03, aB0 + ko);
    ldsm4t(a10, a11, a12, a13, aB1 + ko);
    unsigned b0, b1, b2, b3;
    ldsm4t(b0, b1, b2, b3, bB0 + ko);
    mma16816(acc[0], a00, a01, a02, a03, b0, b1);
    mma16816(acc[1], a00, a01, a02, a03, b2, b3);
    mma16816(acc[8], a10, a11, a12, a13, b0, b1);
    mma16816(acc[9], a10, a11, a12, a13, b2, b3);
    ldsm4t(b0, b1, b2, b3, bB1 + ko);
    mma16816(acc[2],  a00, a01, a02, a03, b0, b1);
    mma16816(acc[3],  a00, a01, a02, a03, b2, b3);
    mma16816(acc[10], a10, a11, a12, a13, b0, b1);
    mma16816(acc[11], a10, a11, a12, a13, b2, b3);
    ldsm4t(b0, b1, b2, b3, bB2 + ko);
    mma16816(acc[4],  a00, a01, a02, a03, b0, b1);
    mma16816(acc[5],  a00, a01, a02, a03, b2, b3);
    mma16816(acc[12], a10, a11, a12, a13, b0, b1);
    mma16816(acc[13], a10, a11, a12, a13, b2, b3);
    ldsm4t(b0, b1, b2, b3, bB3 + ko);
    mma16816(acc[6],  a00, a01, a02, a03, b0, b1);
    mma16816(acc[7],  a00, a01, a02, a03, b2, b3);
    mma16816(acc[14], a10, a11, a12, a13, b0, b1);
    mma16816(acc[15], a10, a11, a12, a13, b2, b3);
  };

  for (int tt = 0; tt < 4; tt++) {
    // stage 4 pieces = row-blocks 2tt (K,V) and 2tt+1 (K,V)
#pragma unroll
    for (int pq = 0; pq < 4; pq++) {
      int p = 4 * tt + pq;
      int rem = 15 - p;
      if (rem >= 5) cp_wait<5>();
      else if (rem == 4) cp_wait<4>();
      else if (rem == 3) cp_wait<3>();
      else if (rem == 2) cp_wait<2>();
      else if (rem == 1) cp_wait<1>();
      else cp_wait<0>();
      const float* zone = (const float*)(zoneB + (p % 6) * 8192);
      bool isK = ((p & 1) == 0);
      __half* dst = isK ? s_k : s_v;
      int rowb = (p >> 1) * 16;
#pragma unroll
      for (int j = 0; j < 2; j++) {
        int cch = tid + j * 256;
        int r = cch >> 5;
        float4 f = *(const float4*)(zone + cch * 4);
        float o0, o1, o2, o3;
        if (isK) {
          o0 = phi_f(f.x, scv.x, biv.x); o1 = phi_f(f.y, scv.y, biv.y);
          o2 = phi_f(f.z, scv.z, biv.z); o3 = phi_f(f.w, scv.w, biv.w);
          z0 += o0; z1 += o1; z2 += o2; z3 += o3;
        } else { o0 = f.x; o1 = f.y; o2 = f.z; o3 = f.w; }
        int rowA = rowb + r;
        int grp = (colf >> 3) ^ (rowA & 7);
        __half2 h0 = __floats2half2_rn(o0, o1), h1 = __floats2half2_rn(o2, o3);
        uint2 pk; pk.x = *(unsigned*)&h0; pk.y = *(unsigned*)&h1;
        *(uint2*)(dst + rowA * 128 + (grp << 3) + (colf & 7)) = pk;
      }
      if (p + 6 < 16) issue(p + 6);
    }
    // deferred mma: slices staged by the barrier at the END of last iteration.
    // Interleaves with the fill above in the same scheduling window.
    if (tt > 0) { mma_slice(2 * tt - 2); mma_slice(2 * tt - 1); }
    __syncthreads();           // pairs 2tt, 2tt+1 fully staged
  }
  mma_slice(6); mma_slice(7);  // tail (staged by final barrier)

  atomicAdd(&s_z[colf], z0); atomicAdd(&s_z[colf + 1], z1);
  atomicAdd(&s_z[colf + 2], z2); atomicAdd(&s_z[colf + 3], z3);
  __syncthreads();

  __half* Sp = g_S + ((size_t)bh * NS_ + c) * (D_ * D_);
#pragma unroll
  for (int jt = 0; jt < 16; jt++) {
    int ms = jt >> 3, j = jt & 7;
    int row = m0 + (ms << 4) + g;
    int ncol = n0 + j * 8 + 2 * t4;
    *(__half2*)(Sp + row * D_ + ncol)       = __floats2half2_rn(acc[jt][0], acc[jt][1]);
    *(__half2*)(Sp + (row + 8) * D_ + ncol) = __floats2half2_rn(acc[jt][2], acc[jt][3]);
  }
  if (tid < 128) g_Z[((size_t)bh * NS_ + c) * D_ + tid] = s_z[tid];
}

// ---------------------------------------------------------------------------
// pass2: exclusive prefix over chunks, vectorized uint4 (8 halves / thread)
// ---------------------------------------------------------------------------
extern "C" __global__ void __launch_bounds__(256)
la_pass2() {
  int t = blockIdx.x * 256 + threadIdx.x;     // 65536 threads
  int bh = t >> 11;
  int idx = (t & 2047) * 8;
  __half* base = g_S + (size_t)bh * NS_ * (D_ * D_) + idx;
  float run[8] = {0.f, 0.f, 0.f, 0.f, 0.f, 0.f, 0.f, 0.f};
  uint4 cur = *(uint4*)base;
#pragma unroll
  for (int s = 0; s < NC_; s++) {
    uint4 nxt = {0, 0, 0, 0};
    if (s < NC_ - 1) nxt = *(uint4*)(base + (size_t)(s + 1) * (D_ * D_));
    const __half2* hp = (const __half2*)&cur;
    float2 f0 = __half22float2(hp[0]), f1 = __half22float2(hp[1]);
    float2 f2 = __half22float2(hp[2]), f3 = __half22float2(hp[3]);
    __half2 o0 = __floats2half2_rn(run[0], run[1]);
    __half2 o1 = __floats2half2_rn(run[2], run[3]);
    __half2 o2 = __floats2half2_rn(run[4], run[5]);
    __half2 o3 = __floats2half2_rn(run[6], run[7]);
    uint4 ov; ov.x = *(unsigned*)&o0; ov.y = *(unsigned*)&o1;
    ov.z = *(unsigned*)&o2; ov.w = *(unsigned*)&o3;
    *(uint4*)(base + (size_t)s * (D_ * D_)) = ov;
    run[0] += f0.x; run[1] += f0.y; run[2] += f1.x; run[3] += f1.y;
    run[4] += f2.x; run[5] += f2.y; run[6] += f3.x; run[7] += f3.y;
    cur = nxt;
  }
  {
    __half2 o0 = __floats2half2_rn(run[0], run[1]);
    __half2 o1 = __floats2half2_rn(run[2], run[3]);
    __half2 o2 = __floats2half2_rn(run[4], run[5]);
    __half2 o3 = __floats2half2_rn(run[6], run[7]);
    uint4 ov; ov.x = *(unsigned*)&o0; ov.y = *(unsigned*)&o1;
    ov.z = *(unsigned*)&o2; ov.w = *(unsigned*)&o3;
    *(uint4*)(base + (size_t)NC_ * (D_ * D_)) = ov;
  }
  if (t < BH_ * 32) {
    int b2 = t >> 5;
    int i4 = (t & 31) * 4;
    float* zb = g_Z + (size_t)b2 * NS_ * D_ + i4;
    float zr0 = 0.f, zr1 = 0.f, zr2 = 0.f, zr3 = 0.f;
    float4 zc = *(float4*)zb;
#pragma unroll
    for (int s = 0; s < NC_; s++) {
      float4 zn = {0.f, 0.f, 0.f, 0.f};
      if (s < NC_ - 1) zn = *(float4*)(zb + (size_t)(s + 1) * D_);
      float4 ov; ov.x = zr0; ov.y = zr1; ov.z = zr2; ov.w = zr3;
      *(float4*)(zb + (size_t)s * D_) = ov;
      zr0 += zc.x; zr1 += zc.y; zr2 += zc.z; zr3 += zc.w;
      zc = zn;
    }
    float4 ov; ov.x = zr0; ov.y = zr1; ov.z = zr2; ov.w = zr3;
    *(float4*)(zb + (size_t)NC_ * D_) = ov;
  }
}

// ---------------------------------------------------------------------------
// pass3 (R14 exact): 2 CTAs per 128-row chunk; blockIdx.x = 2c+half for
// S L2 reuse. smem: q16 k16 v16 S32 zones[4x8] z/den = 115456B
// ---------------------------------------------------------------------------
extern "C" __global__ void __launch_bounds__(256, 2)
la_pass3(const float* __restrict__ Q, const float* __restrict__ K,
         const float* __restrict__ V, const float* __restrict__ scale,
         const float* __restrict__ bias, float* __restrict__ out) {
  int x = blockIdx.x, c = x >> 1, half = x & 1;
  int bh = blockIdx.y, h = bh & (H_ - 1);
  extern __shared__ char smem[];
  __half* s_q = (__half*)smem;                 // 16384 B (64 rows)
  __half* s_k = s_q + 8192;                    // +16384 B
  __half* s_v = s_k + 8192;                    // +16384 B
  __half* s_S = s_v + 8192;                    // +32768 B (offset 49152)
  char*   zoneB = smem + 81920;                // 4 x 8192 B
  float*  s_z   = (float*)(smem + 114688);     // 128 floats
  float*  s_den = s_z + 128;                   // 64 floats
  unsigned sb = su32(smem);
  int tid = threadIdx.x, lane = tid & 31;

  size_t qoff = ((size_t)bh * L_ + (size_t)c * CH_ + half * 64) * D_;
  size_t koff = ((size_t)bh * L_ + (size_t)c * CH_ + (half ? 96 : 0)) * D_;
  int nk = half ? 2 : 4;
  int P = 4 + 2 * nk;

  // S via cp.async, 2 groups (complete before piece 0 per FIFO group order)
  const __half* Sp = g_S + ((size_t)bh * NS_ + c + half) * (D_ * D_);
  for (int gq = 0; gq < 2; gq++) {
#pragma unroll
    for (int j = 0; j < 4; j++) {
      int ch = gq * 1024 + j * 256 + tid;
      int d = ch >> 4, e8 = ch & 15;
      unsigned dst = sb + 49152u + (unsigned)((d * 128 + ((e8 ^ (d & 7)) << 3)) * 2);
      cpasync16(dst, Sp + ch * 8);
    }
    cpcommit();
  }
  auto issue = [&](int p) {
    const float* src;
    if (p < 4)           src = Q + qoff + (size_t)p * 2048;
    else if (p < 4 + nk) src = K + koff + (size_t)(p - 4) * 2048;
    else                 src = V + koff + (size_t)(p - 4 - nk) * 2048;
    unsigned zb = sb + 81920u + (unsigned)(p & 3) * 8192u;
    cpasync16(zb + tid * 16, src + tid * 4);
    cpasync16(zb + (tid + 256) * 16, src + (tid + 256) * 4);
    cpcommit();
  };
  issue(0); issue(1); issue(2); issue(3);

  int colf = (tid & 31) * 4;
  float4 scv = *(const float4*)(scale + h * D_ + colf);
  float4 biv = *(const float4*)(bias  + h * D_ + colf);
  if (tid < 32)
    *(float4*)&s_z[4 * tid] =
      *(const float4*)(g_Z + ((size_t)bh * NS_ + c + half) * D_ + 4 * tid);
  if (tid < 64) s_den[tid] = 0.f;

  auto step = [&](int p) {  // wait piece p, convert+store, refill
    int rem = P - 1 - p;
    if (rem >= 3) cp_wait<3>();
    else if (rem == 2) cp_wait<2>();
    else if (rem == 1) cp_wait<1>();
    else cp_wait<0>();
    const float* zone = (const float*)(zoneB + (p & 3) * 8192);
    __half* dst; int rowb; bool doPhi;
    if (p < 4)           { dst = s_q; rowb = p * 16;            doPhi = true;  }
    else if (p < 4 + nk) { dst = s_k; rowb = (p - 4) * 16;      doPhi = true;  }
    else                 { dst = s_v; rowb = (p - 4 - nk) * 16; doPhi = false; }
#pragma unroll
    for (int j = 0; j < 2; j++) {
      int cch = tid + j * 256;
      int r = cch >> 5;
      float4 f = *(const float4*)(zone + cch * 4);
      float o0, o1, o2, o3;
      if (doPhi) {
        o0 = phi_f(f.x, scv.x, biv.x); o1 = phi_f(f.y, scv.y, biv.y);
        o2 = phi_f(f.z, scv.z, biv.z); o3 = phi_f(f.w, scv.w, biv.w);
      } else { o0 = f.x; o1 = f.y; o2 = f.z; o3 = f.w; }
      int rowA = rowb + r;
      int grp = (colf >> 3) ^ (rowA & 7);
      __half2 h0 = __floats2half2_rn(o0, o1), h1 = __floats2half2_rn(o2, o3);
      uint2 pk; pk.x = *(unsigned*)&h0; pk.y = *(unsigned*)&h1;
      *(uint2*)(dst + rowA * 128 + (grp << 3) + (colf & 7)) = pk;
    }
    if (p + 4 < P) issue(p + 4);
  };

  int w = tid >> 5, g = lane >> 2, t4 = lane & 3;
  int mt = w & 3, nh = w >> 2, m0 = mt << 4;
  int jpmax = half ? (2 * (1 - (mt >> 1))) : (2 * ((mt >> 1) + 1));
  float sgn = half ? -1.f : 1.f;
  int l7 = lane & 7, cb3 = lane >> 4, ca3 = (lane >> 3) & 1;

  int rq = m0 + (lane & 15), rq7 = rq & 7;
  unsigned aQbase = sb + (unsigned)(rq * 256);
  int rA = (lane & 7) + 8 * (lane >> 4);
  unsigned bKbase = sb + 16384u + (unsigned)(rA * 256);
  int rB = (lane & 7) + 8 * ((lane >> 3) & 1);
  unsigned bVbase = sb + 32768u + (unsigned)(rB * 256);
  unsigned bSbase = sb + 49152u + (unsigned)(rB * 256);

  float o[8][4];
  float p_[8][4];
#pragma unroll
  for (int jt = 0; jt < 8; jt++) {
    o[jt][0] = o[jt][1] = o[jt][2] = o[jt][3] = 0.f;
    p_[jt][0] = p_[jt][1] = p_[jt][2] = p_[jt][3] = 0.f;
  }

  auto ochunk = [&](int k0c) {  // O += phi_q(:, k0) @ S(k0, nhalf)
    int k0 = k0c * 16;
    unsigned a0, a1, a2, a3;
    ldsm4(a0, a1, a2, a3, aQbase + (unsigned)(((2 * k0c + cb3) ^ rq7) << 4));
#pragma unroll
    for (int jp = 0; jp < 4; jp++) {
      unsigned b0, b1, b2, b3;
      ldsm4t(b0, b1, b2, b3, bSbase + (unsigned)(k0 * 256 + (((nh * 8 + 2 * jp + cb3) ^ l7) << 4)));
      mma16816(o[2 * jp],     a0, a1, a2, a3, b0, b1);
      mma16816(o[2 * jp + 1], a0, a1, a2, a3, b2, b3);
    }
  };
  auto pchunk = [&](int k0c) {  // P += phi_q(:, k0) @ phi_k(:, k0)^T
    if (jpmax == 0) return;
    unsigned a0, a1, a2, a3;
    ldsm4(a0, a1, a2, a3, aQbase + (unsigned)(((2 * k0c + cb3) ^ rq7) << 4));
#pragma unroll
    for (int jp = 0; jp < 4; jp++) {
      if (jp < jpmax) {
        unsigned b0, b1, b2, b3;
        ldsm4(b0, b1, b2, b3, bKbase + (unsigned)(jp * 4096 + (((2 * k0c + ca3) ^ l7) << 4)));
        mma16816(p_[2 * jp],     a0, a1, a2, a3, b0, b1);
        mma16816(p_[2 * jp + 1], a0, a1, a2, a3, b2, b3);
      }
    }
  };

  // Phase A: q pieces
  step(0); step(1); step(2); step(3);
  __syncthreads();

  // den base: phi_q[r] . Z  (4 threads per row, swizzled reads)
  {
    int r = tid >> 2, ds = (tid & 3) << 5;
    float acc = 0.f;
#pragma unroll
    for (int j = 0; j < 16; j++) {
      int col = ds + 2 * j;
      int grp = ((col >> 3) ^ (r & 7));
      float2 f = __half22float2(*(const __half2*)(s_q + r * 128 + (grp << 3) + (col & 7)));
      acc += f.x * s_z[col] + f.y * s_z[col + 1];
    }
    atomicAdd(&s_den[r], acc);
  }

  // Phase B: k pieces interleaved with O chunks 0..3
  if (half == 0) {
    for (int i = 0; i < 4; i++) { step(4 + i); ochunk(i); }
  } else {
    for (int i = 0; i < 2; i++) { step(4 + i); ochunk(2 * i); ochunk(2 * i + 1); }
  }
  __syncthreads();   // k fully staged

  // Phase C: v pieces interleaved with O chunks 4..7 and P chunks 0..7
  if (half == 0) {
    for (int i = 0; i < 4; i++) {
      step(8 + i); ochunk(4 + i); pchunk(2 * i); pchunk(2 * i + 1);
    }
  } else {
    for (int i = 0; i < 2; i++) {
      step(6 + i); ochunk(4 + 2 * i); ochunk(5 + 2 * i);
      pchunk(4 * i); pchunk(4 * i + 1); pchunk(4 * i + 2); pchunk(4 * i + 3);
    }
  }
  __syncthreads();   // v fully staged

  // signed rowsums + signed fp16 pack of P into A fragments
  float rs0 = 0.f, rs1 = 0.f;
  unsigned ph[8][2];
#pragma unroll
  for (int jt = 0; jt < 8; jt++) {
    float v0 = sgn * p_[jt][0], v1 = sgn * p_[jt][1];
    float v2 = sgn * p_[jt][2], v3 = sgn * p_[jt][3];
    rs0 += v0 + v1; rs1 += v2 + v3;
    __half2 h0 = __floats2half2_rn(v0, v1);
    __half2 h1 = __floats2half2_rn(v2, v3);
    ph[jt][0] = *(unsigned*)&h0;
    ph[jt][1] = *(unsigned*)&h1;
  }
  rs0 += __shfl_xor_sync(0xffffffffu, rs0, 1);
  rs0 += __shfl_xor_sync(0xffffffffu, rs0, 2);
  rs1 += __shfl_xor_sync(0xffffffffu, rs1, 1);
  rs1 += __shfl_xor_sync(0xffffffffu, rs1, 2);

  // PV gemm: O +/- = P @ V
#pragma unroll
  for (int kt = 0; kt < 4; kt++) {
    if (kt < jpmax) {
      unsigned a0 = ph[2 * kt][0], a1 = ph[2 * kt][1];
      unsigned a2 = ph[2 * kt + 1][0], a3 = ph[2 * kt + 1][1];
#pragma unroll
      for (int jp = 0; jp < 4; jp++) {
        unsigned b0, b1, b2, b3;
        ldsm4t(b0, b1, b2, b3, bVbase + (unsigned)(kt * 4096 + (((nh * 8 + 2 * jp + cb3) ^ l7) << 4)));
        mma16816(o[2 * jp],     a0, a1, a2, a3, b0, b1);
        mma16816(o[2 * jp + 1], a0, a1, a2, a3, b2, b3);
      }
    }
  }

  // epilogue
  float inv0 = 1.f / fmaxf(s_den[m0 + g]     + rs0, EPS_);
  float inv1 = 1.f / fmaxf(s_den[m0 + g + 8] + rs1, EPS_);
  float* op = out + qoff;
#pragma unroll
  for (int jt = 0; jt < 8; jt++) {
    int n0 = nh * 64 + jt * 8 + 2 * t4;
    float2 v0; v0.x = o[jt][0] * inv0; v0.y = o[jt][1] * inv0;
    float2 v1; v1.x = o[jt][2] * inv1; v1.y = o[jt][3] * inv1;
    *(float2*)(op + (m0 + g) * D_ + n0)     = v0;
    *(float2*)(op + (m0 + g + 8) * D_ + n0) = v1;
  }
}

// ---------------------------------------------------------------------------
#define P1_SMEM 115200
#define P3_SMEM 115456

extern "C" void kernel_launch(void* const* d_in, const int* in_sizes, int n_in,
                              void* d_out, int out_size) {
  (void)in_sizes; (void)n_in; (void)out_size;
  const float* q  = (const float*)d_in[0];
  const float* k  = (const float*)d_in[1];
  const float* v  = (const float*)d_in[2];
  const float* sc = (const float*)d_in[3];
  const float* bi = (const float*)d_in[4];
  float* out = (float*)d_out;

  static bool attrs_set = false;
  if (!attrs_set) {
    cudaFuncSetAttribute(la_pass1, cudaFuncAttributeMaxDynamicSharedMemorySize, P1_SMEM);
    cudaFuncSetAttribute(la_pass3, cudaFuncAttributeMaxDynamicSharedMemorySize, P3_SMEM);
    attrs_set = true;
  }

  la_pass1<<<dim3(NC_, BH_), 256, P1_SMEM>>>(k, v, sc, bi);
  la_pass2<<<(BH_ * D_ * D_ / 8) / 256, 256>>>();
  la_pass3<<<dim3(2 * NC_, BH_), 256, P3_SMEM>>>(q, k, v, sc, bi, out);
}

// round 16
// speedup vs baseline: 1.0380x; 1.0380x over previous
#include <cuda_runtime.h>
#include <cuda_fp16.h>

#define BH_  32
#define H_   16
#define L_   4096
#define D_   128
#define CH_  128
#define NC_  32
#define NS_  (NC_ + 1)
#define EPS_ 1e-6f

// scratch: per-chunk state sums -> exclusive prefix (fp16), Z in fp32
__device__ __half g_S[(size_t)BH_ * NS_ * D_ * D_];
__device__ float  g_Z[(size_t)BH_ * NS_ * D_];

__device__ __forceinline__ unsigned su32(const void* p) {
  return (unsigned)__cvta_generic_to_shared(p);
}
__device__ __forceinline__ void cpasync16(unsigned dst, const void* src) {
  asm volatile("cp.async.cg.shared.global [%0], [%1], 16;\n" :: "r"(dst), "l"(src));
}
__device__ __forceinline__ void cpcommit() {
  asm volatile("cp.async.commit_group;\n");
}
template<int N> __device__ __forceinline__ void cp_wait() {
  asm volatile("cp.async.wait_group %0;\n" :: "n"(N));
}
__device__ __forceinline__ void ldsm4(unsigned& r0, unsigned& r1, unsigned& r2, unsigned& r3, unsigned a) {
  asm volatile("ldmatrix.sync.aligned.m8n8.x4.shared.b16 {%0,%1,%2,%3},[%4];"
               : "=r"(r0), "=r"(r1), "=r"(r2), "=r"(r3) : "r"(a));
}
__device__ __forceinline__ void ldsm4t(unsigned& r0, unsigned& r1, unsigned& r2, unsigned& r3, unsigned a) {
  asm volatile("ldmatrix.sync.aligned.m8n8.x4.trans.shared.b16 {%0,%1,%2,%3},[%4];"
               : "=r"(r0), "=r"(r1), "=r"(r2), "=r"(r3) : "r"(a));
}
__device__ __forceinline__ void mma16816(float c[4],
    unsigned a0, unsigned a1, unsigned a2, unsigned a3,
    unsigned b0, unsigned b1) {
  asm volatile(
    "mma.sync.aligned.m16n8k16.row.col.f32.f16.f16.f32 "
    "{%0,%1,%2,%3},{%4,%5,%6,%7},{%8,%9},{%0,%1,%2,%3};\n"
    : "+f"(c[0]), "+f"(c[1]), "+f"(c[2]), "+f"(c[3])
    : "r"(a0), "r"(a1), "r"(a2), "r"(a3), "r"(b0), "r"(b1));
}

__device__ __forceinline__ float phi_f(float x, float s, float b) {
  float y = fmaf(x, s, b);
  float p = (y > 0.f) ? (y + 1.f) : __expf(y);
  return fminf(p, 10.f);
}

// Swizzled fp16 tiles: row stride 128 halves; off(r,c) = r*128 + (((c>>3)^(r&7))<<3) + (c&7)

// ---------------------------------------------------------------------------
// pass1 (R15 exact): S_c = phi_k^T V (fp16), Z_c = colsum(phi_k)
// Deferred mma: iteration tt stages pieces 4tt..4tt+3 and runs mma for slices
// 2tt-2, 2tt-1 interleaved with the fill. Tail mma after the loop.
// smem: s_k[32KB] s_v[32KB] zones[6x8KB] z[512B] = 115200B
// ---------------------------------------------------------------------------
extern "C" __global__ void __launch_bounds__(256, 2)
la_pass1(const float* __restrict__ K, const float* __restrict__ V,
         const float* __restrict__ scale, const float* __restrict__ bias) {
  int c = blockIdx.x, bh = blockIdx.y, h = bh & (H_ - 1);
  extern __shared__ char smem[];
  __half* s_k = (__half*)smem;                 // 32768 B, swizzled 128x128
  __half* s_v = s_k + 128 * 128;               // +32768 B
  char*   zoneB = smem + 65536;                // 6 x 8192 B raw fp32
  float*  s_z  = (float*)(smem + 114688);      // 128 floats
  unsigned sb = su32(smem);
  int tid = threadIdx.x, lane = tid & 31;
  size_t off = ((size_t)bh * L_ + (size_t)c * CH_) * D_;

  // piece p: even -> K row-block p/2 ; odd -> V row-block p/2
  auto issue = [&](int p) {
    int t = p >> 1;
    const float* src = ((p & 1) == 0) ? (K + off + (size_t)t * 2048)
                                      : (V + off + (size_t)t * 2048);
    unsigned zb = sb + 65536u + (unsigned)(p % 6) * 8192u;
    cpasync16(zb + tid * 16, src + tid * 4);
    cpasync16(zb + (tid + 256) * 16, src + (tid + 256) * 4);
    cpcommit();
  };
  issue(0); issue(1); issue(2); issue(3); issue(4); issue(5);

  int colf = (tid & 31) * 4;
  float4 scv = *(const float4*)(scale + h * D_ + colf);
  float4 biv = *(const float4*)(bias  + h * D_ + colf);
  if (tid < 128) s_z[tid] = 0.f;
  float z0 = 0.f, z1 = 0.f, z2 = 0.f, z3 = 0.f;

  // mma frag setup (m32 x n64 warp tile)
  int w = tid >> 5, g = lane >> 2, t4 = lane & 3;
  int wm = w & 3, wn = w >> 2;
  int m0 = wm << 5, n0 = wn << 6;
  int l7 = lane & 7, ca3 = (lane >> 3) & 1, cb3 = lane >> 4;
  int rA = l7 + 8 * cb3;
  int rB = l7 + 8 * ca3;
  unsigned aB0 = sb + (unsigned)(rA * 256 + (((4 * wm + ca3) ^ l7) << 4));
  unsigned aB1 = sb + (unsigned)(rA * 256 + (((4 * wm + 2 + ca3) ^ l7) << 4));
  unsigned bB0 = sb + 32768u + (unsigned)(rB * 256 + (((8 * wn + cb3) ^ l7) << 4));
  unsigned bB1 = sb + 32768u + (unsigned)(rB * 256 + (((8 * wn + 2 + cb3) ^ l7) << 4));
  unsigned bB2 = sb + 32768u + (unsigned)(rB * 256 + (((8 * wn + 4 + cb3) ^ l7) << 4));
  unsigned bB3 = sb + 32768u + (unsigned)(rB * 256 + (((8 * wn + 6 + cb3) ^ l7) << 4));

  float acc[16][4];
#pragma unroll
  for (int jt = 0; jt < 16; jt++) { acc[jt][0] = acc[jt][1] = acc[jt][2] = acc[jt][3] = 0.f; }

  auto mma_slice = [&](int s) {
    unsigned ko = (unsigned)(s * 16 * 256);
    unsigned a00, a01, a02, a03, a10, a11, a12, a13;
    ldsm4t(a00, a01, a02, a03, aB0 + ko);
    ldsm4t(a10, a11, a12, a13, aB1 + ko);
    unsigned b0, b1, b2, b3;
    ldsm4t(b0, b1, b2, b3, bB0 + ko);
    mma16816(acc[0], a00, a01, a02, a03, b0, b1);
    mma16816(acc[1], a00, a01, a02, a03, b2, b3);
    mma16816(acc[8], a10, a11, a12, a13, b0, b1);
    mma16816(acc[9], a10, a11, a12, a13, b2, b3);
    ldsm4t(b0, b1, b2, b3, bB1 + ko);
    mma16816(acc[2],  a00, a01, a02, a03, b0, b1);
    mma16816(acc[3],  a00, a01, a02, a03, b2, b3);
    mma16816(acc[10], a10, a11, a12, a13, b0, b1);
    mma16816(acc[11], a10, a11, a12, a13, b2, b3);
    ldsm4t(b0, b1, b2, b3, bB2 + ko);
    mma16816(acc[4],  a00, a01, a02, a03, b0, b1);
    mma16816(acc[5],  a00, a01, a02, a03, b2, b3);
    mma16816(acc[12], a10, a11, a12, a13, b0, b1);
    mma16816(acc[13], a10, a11, a12, a13, b2, b3);
    ldsm4t(b0, b1, b2, b3, bB3 + ko);
    mma16816(acc[6],  a00, a01, a02, a03, b0, b1);
    mma16816(acc[7],  a00, a01, a02, a03, b2, b3);
    mma16816(acc[14], a10, a11, a12, a13, b0, b1);
    mma16816(acc[15], a10, a11, a12, a13, b2, b3);
  };

  for (int tt = 0; tt < 4; tt++) {
#pragma unroll
    for (int pq = 0; pq < 4; pq++) {
      int p = 4 * tt + pq;
      int rem = 15 - p;
      if (rem >= 5) cp_wait<5>();
      else if (rem == 4) cp_wait<4>();
      else if (rem == 3) cp_wait<3>();
      else if (rem == 2) cp_wait<2>();
      else if (rem == 1) cp_wait<1>();
      else cp_wait<0>();
      const float* zone = (const float*)(zoneB + (p % 6) * 8192);
      bool isK = ((p & 1) == 0);
      __half* dst = isK ? s_k : s_v;
      int rowb = (p >> 1) * 16;
#pragma unroll
      for (int j = 0; j < 2; j++) {
        int cch = tid + j * 256;
        int r = cch >> 5;
        float4 f = *(const float4*)(zone + cch * 4);
        float o0, o1, o2, o3;
        if (isK) {
          o0 = phi_f(f.x, scv.x, biv.x); o1 = phi_f(f.y, scv.y, biv.y);
          o2 = phi_f(f.z, scv.z, biv.z); o3 = phi_f(f.w, scv.w, biv.w);
          z0 += o0; z1 += o1; z2 += o2; z3 += o3;
        } else { o0 = f.x; o1 = f.y; o2 = f.z; o3 = f.w; }
        int rowA = rowb + r;
        int grp = (colf >> 3) ^ (rowA & 7);
        __half2 h0 = __floats2half2_rn(o0, o1), h1 = __floats2half2_rn(o2, o3);
        uint2 pk; pk.x = *(unsigned*)&h0; pk.y = *(unsigned*)&h1;
        *(uint2*)(dst + rowA * 128 + (grp << 3) + (colf & 7)) = pk;
      }
      if (p + 6 < 16) issue(p + 6);
    }
    if (tt > 0) { mma_slice(2 * tt - 2); mma_slice(2 * tt - 1); }
    __syncthreads();           // pairs 2tt, 2tt+1 fully staged
  }
  mma_slice(6); mma_slice(7);  // tail (staged by final barrier)

  atomicAdd(&s_z[colf], z0); atomicAdd(&s_z[colf + 1], z1);
  atomicAdd(&s_z[colf + 2], z2); atomicAdd(&s_z[colf + 3], z3);
  __syncthreads();

  __half* Sp = g_S + ((size_t)bh * NS_ + c) * (D_ * D_);
#pragma unroll
  for (int jt = 0; jt < 16; jt++) {
    int ms = jt >> 3, j = jt & 7;
    int row = m0 + (ms << 4) + g;
    int ncol = n0 + j * 8 + 2 * t4;
    *(__half2*)(Sp + row * D_ + ncol)       = __floats2half2_rn(acc[jt][0], acc[jt][1]);
    *(__half2*)(Sp + (row + 8) * D_ + ncol) = __floats2half2_rn(acc[jt][2], acc[jt][3]);
  }
  if (tid < 128) g_Z[((size_t)bh * NS_ + c) * D_ + tid] = s_z[tid];
}

// ---------------------------------------------------------------------------
// pass2: exclusive prefix over chunks, vectorized uint4 (8 halves / thread)
// ---------------------------------------------------------------------------
extern "C" __global__ void __launch_bounds__(256)
la_pass2() {
  int t = blockIdx.x * 256 + threadIdx.x;     // 65536 threads
  int bh = t >> 11;
  int idx = (t & 2047) * 8;
  __half* base = g_S + (size_t)bh * NS_ * (D_ * D_) + idx;
  float run[8] = {0.f, 0.f, 0.f, 0.f, 0.f, 0.f, 0.f, 0.f};
  uint4 cur = *(uint4*)base;
#pragma unroll
  for (int s = 0; s < NC_; s++) {
    uint4 nxt = {0, 0, 0, 0};
    if (s < NC_ - 1) nxt = *(uint4*)(base + (size_t)(s + 1) * (D_ * D_));
    const __half2* hp = (const __half2*)&cur;
    float2 f0 = __half22float2(hp[0]), f1 = __half22float2(hp[1]);
    float2 f2 = __half22float2(hp[2]), f3 = __half22float2(hp[3]);
    __half2 o0 = __floats2half2_rn(run[0], run[1]);
    __half2 o1 = __floats2half2_rn(run[2], run[3]);
    __half2 o2 = __floats2half2_rn(run[4], run[5]);
    __half2 o3 = __floats2half2_rn(run[6], run[7]);
    uint4 ov; ov.x = *(unsigned*)&o0; ov.y = *(unsigned*)&o1;
    ov.z = *(unsigned*)&o2; ov.w = *(unsigned*)&o3;
    *(uint4*)(base + (size_t)s * (D_ * D_)) = ov;
    run[0] += f0.x; run[1] += f0.y; run[2] += f1.x; run[3] += f1.y;
    run[4] += f2.x; run[5] += f2.y; run[6] += f3.x; run[7] += f3.y;
    cur = nxt;
  }
  {
    __half2 o0 = __floats2half2_rn(run[0], run[1]);
    __half2 o1 = __floats2half2_rn(run[2], run[3]);
    __half2 o2 = __floats2half2_rn(run[4], run[5]);
    __half2 o3 = __floats2half2_rn(run[6], run[7]);
    uint4 ov; ov.x = *(unsigned*)&o0; ov.y = *(unsigned*)&o1;
    ov.z = *(unsigned*)&o2; ov.w = *(unsigned*)&o3;
    *(uint4*)(base + (size_t)NC_ * (D_ * D_)) = ov;
  }
  if (t < BH_ * 32) {
    int b2 = t >> 5;
    int i4 = (t & 31) * 4;
    float* zb = g_Z + (size_t)b2 * NS_ * D_ + i4;
    float zr0 = 0.f, zr1 = 0.f, zr2 = 0.f, zr3 = 0.f;
    float4 zc = *(float4*)zb;
#pragma unroll
    for (int s = 0; s < NC_; s++) {
      float4 zn = {0.f, 0.f, 0.f, 0.f};
      if (s < NC_ - 1) zn = *(float4*)(zb + (size_t)(s + 1) * D_);
      float4 ov; ov.x = zr0; ov.y = zr1; ov.z = zr2; ov.w = zr3;
      *(float4*)(zb + (size_t)s * D_) = ov;
      zr0 += zc.x; zr1 += zc.y; zr2 += zc.z; zr3 += zc.w;
      zc = zn;
    }
    float4 ov; ov.x = zr0; ov.y = zr1; ov.z = zr2; ov.w = zr3;
    *(float4*)(zb + (size_t)NC_ * D_) = ov;
  }
}

// ---------------------------------------------------------------------------
// pass3: R14 core + FUSED DEN: den_base[r] computed inside the q-fill
// (per-thread partial dot with Z from gmem, warp reduce, lane-0 store).
// Removes the dedicated den phase, s_z staging, and all den atomics.
// blockIdx.x = 2c+half for S L2 reuse.
// smem: q16 k16 v16 S32 zones[4x8] den[256B] = 114944B
// ---------------------------------------------------------------------------
extern "C" __global__ void __launch_bounds__(256, 2)
la_pass3(const float* __restrict__ Q, const float* __restrict__ K,
         const float* __restrict__ V, const float* __restrict__ scale,
         const float* __restrict__ bias, float* __restrict__ out) {
  int x = blockIdx.x, c = x >> 1, half = x & 1;
  int bh = blockIdx.y, h = bh & (H_ - 1);
  extern __shared__ char smem[];
  __half* s_q = (__half*)smem;                 // 16384 B (64 rows)
  __half* s_k = s_q + 8192;                    // +16384 B
  __half* s_v = s_k + 8192;                    // +16384 B
  __half* s_S = s_v + 8192;                    // +32768 B (offset 49152)
  char*   zoneB = smem + 81920;                // 4 x 8192 B
  float*  s_den = (float*)(smem + 114688);     // 64 floats
  unsigned sb = su32(smem);
  int tid = threadIdx.x, lane = tid & 31;

  size_t qoff = ((size_t)bh * L_ + (size_t)c * CH_ + half * 64) * D_;
  size_t koff = ((size_t)bh * L_ + (size_t)c * CH_ + (half ? 96 : 0)) * D_;
  int nk = half ? 2 : 4;
  int P = 4 + 2 * nk;

  // S via cp.async, 2 groups (complete before piece 0 per FIFO group order)
  const __half* Sp = g_S + ((size_t)bh * NS_ + c + half) * (D_ * D_);
  for (int gq = 0; gq < 2; gq++) {
#pragma unroll
    for (int j = 0; j < 4; j++) {
      int ch = gq * 1024 + j * 256 + tid;
      int d = ch >> 4, e8 = ch & 15;
      unsigned dst = sb + 49152u + (unsigned)((d * 128 + ((e8 ^ (d & 7)) << 3)) * 2);
      cpasync16(dst, Sp + ch * 8);
    }
    cpcommit();
  }
  auto issue = [&](int p) {
    const float* src;
    if (p < 4)           src = Q + qoff + (size_t)p * 2048;
    else if (p < 4 + nk) src = K + koff + (size_t)(p - 4) * 2048;
    else                 src = V + koff + (size_t)(p - 4 - nk) * 2048;
    unsigned zb = sb + 81920u + (unsigned)(p & 3) * 8192u;
    cpasync16(zb + tid * 16, src + tid * 4);
    cpasync16(zb + (tid + 256) * 16, src + (tid + 256) * 4);
    cpcommit();
  };
  issue(0); issue(1); issue(2); issue(3);

  int colf = (tid & 31) * 4;
  float4 scv = *(const float4*)(scale + h * D_ + colf);
  float4 biv = *(const float4*)(bias  + h * D_ + colf);
  // Z for this CTA's slot, this thread's 4 columns (L2-broadcast)
  float4 zv  = *(const float4*)(g_Z + ((size_t)bh * NS_ + c + half) * D_ + colf);

  auto step = [&](int p) {  // wait piece p, convert+store (+den for q), refill
    int rem = P - 1 - p;
    if (rem >= 3) cp_wait<3>();
    else if (rem == 2) cp_wait<2>();
    else if (rem == 1) cp_wait<1>();
    else cp_wait<0>();
    const float* zone = (const float*)(zoneB + (p & 3) * 8192);
    __half* dst; int rowb; bool doPhi;
    if (p < 4)           { dst = s_q; rowb = p * 16;            doPhi = true;  }
    else if (p < 4 + nk) { dst = s_k; rowb = (p - 4) * 16;      doPhi = true;  }
    else                 { dst = s_v; rowb = (p - 4 - nk) * 16; doPhi = false; }
#pragma unroll
    for (int j = 0; j < 2; j++) {
      int cch = tid + j * 256;
      int r = cch >> 5;
      float4 f = *(const float4*)(zone + cch * 4);
      float o0, o1, o2, o3;
      if (doPhi) {
        o0 = phi_f(f.x, scv.x, biv.x); o1 = phi_f(f.y, scv.y, biv.y);
        o2 = phi_f(f.z, scv.z, biv.z); o3 = phi_f(f.w, scv.w, biv.w);
      } else { o0 = f.x; o1 = f.y; o2 = f.z; o3 = f.w; }
      int rowA = rowb + r;
      int grp = (colf >> 3) ^ (rowA & 7);
      __half2 h0 = __floats2half2_rn(o0, o1), h1 = __floats2half2_rn(o2, o3);
      uint2 pk; pk.x = *(unsigned*)&h0; pk.y = *(unsigned*)&h1;
      *(uint2*)(dst + rowA * 128 + (grp << 3) + (colf & 7)) = pk;
      if (p < 4) {  // fused den: each row owned by exactly one (piece,warp,j)
        float qd = o0 * zv.x + o1 * zv.y + o2 * zv.z + o3 * zv.w;
#pragma unroll
        for (int s2 = 16; s2; s2 >>= 1) qd += __shfl_xor_sync(0xffffffffu, qd, s2);
        if (lane == 0) s_den[rowA] = qd;   // single writer per row
      }
    }
    if (p + 4 < P) issue(p + 4);
  };

  int w = tid >> 5, g = lane >> 2, t4 = lane & 3;
  int mt = w & 3, nh = w >> 2, m0 = mt << 4;
  int jpmax = half ? (2 * (1 - (mt >> 1))) : (2 * ((mt >> 1) + 1));
  float sgn = half ? -1.f : 1.f;
  int l7 = lane & 7, cb3 = lane >> 4, ca3 = (lane >> 3) & 1;

  int rq = m0 + (lane & 15), rq7 = rq & 7;
  unsigned aQbase = sb + (unsigned)(rq * 256);
  int rA = (lane & 7) + 8 * (lane >> 4);
  unsigned bKbase = sb + 16384u + (unsigned)(rA * 256);
  int rB = (lane & 7) + 8 * ((lane >> 3) & 1);
  unsigned bVbase = sb + 32768u + (unsigned)(rB * 256);
  unsigned bSbase = sb + 49152u + (unsigned)(rB * 256);

  float o[8][4];
  float p_[8][4];
#pragma unroll
  for (int jt = 0; jt < 8; jt++) {
    o[jt][0] = o[jt][1] = o[jt][2] = o[jt][3] = 0.f;
    p_[jt][0] = p_[jt][1] = p_[jt][2] = p_[jt][3] = 0.f;
  }

  auto ochunk = [&](int k0c) {  // O += phi_q(:, k0) @ S(k0, nhalf)
    int k0 = k0c * 16;
    unsigned a0, a1, a2, a3;
    ldsm4(a0, a1, a2, a3, aQbase + (unsigned)(((2 * k0c + cb3) ^ rq7) << 4));
#pragma unroll
    for (int jp = 0; jp < 4; jp++) {
      unsigned b0, b1, b2, b3;
      ldsm4t(b0, b1, b2, b3, bSbase + (unsigned)(k0 * 256 + (((nh * 8 + 2 * jp + cb3) ^ l7) << 4)));
      mma16816(o[2 * jp],     a0, a1, a2, a3, b0, b1);
      mma16816(o[2 * jp + 1], a0, a1, a2, a3, b2, b3);
    }
  };
  auto pchunk = [&](int k0c) {  // P += phi_q(:, k0) @ phi_k(:, k0)^T
    if (jpmax == 0) return;
    unsigned a0, a1, a2, a3;
    ldsm4(a0, a1, a2, a3, aQbase + (unsigned)(((2 * k0c + cb3) ^ rq7) << 4));
#pragma unroll
    for (int jp = 0; jp < 4; jp++) {
      if (jp < jpmax) {
        unsigned b0, b1, b2, b3;
        ldsm4(b0, b1, b2, b3, bKbase + (unsigned)(jp * 4096 + (((2 * k0c + ca3) ^ l7) << 4)));
        mma16816(p_[2 * jp],     a0, a1, a2, a3, b0, b1);
        mma16816(p_[2 * jp + 1], a0, a1, a2, a3, b2, b3);
      }
    }
  };

  // Phase A: q pieces (den fused into the fill)
  step(0); step(1); step(2); step(3);
  __syncthreads();

  // Phase B: k pieces interleaved with O chunks 0..3
  if (half == 0) {
    for (int i = 0; i < 4; i++) { step(4 + i); ochunk(i); }
  } else {
    for (int i = 0; i < 2; i++) { step(4 + i); ochunk(2 * i); ochunk(2 * i + 1); }
  }
  __syncthreads();   // k fully staged

  // Phase C: v pieces interleaved with O chunks 4..7 and P chunks 0..7
  if (half == 0) {
    for (int i = 0; i < 4; i++) {
      step(8 + i); ochunk(4 + i); pchunk(2 * i); pchunk(2 * i + 1);
    }
  } else {
    for (int i = 0; i < 2; i++) {
      step(6 + i); ochunk(4 + 2 * i); ochunk(5 + 2 * i);
      pchunk(4 * i); pchunk(4 * i + 1); pchunk(4 * i + 2); pchunk(4 * i + 3);
    }
  }
  __syncthreads();   // v fully staged

  // signed rowsums + signed fp16 pack of P into A fragments
  float rs0 = 0.f, rs1 = 0.f;
  unsigned ph[8][2];
#pragma unroll
  for (int jt = 0; jt < 8; jt++) {
    float v0 = sgn * p_[jt][0], v1 = sgn * p_[jt][1];
    float v2 = sgn * p_[jt][2], v3 = sgn * p_[jt][3];
    rs0 += v0 + v1; rs1 += v2 + v3;
    __half2 h0 = __floats2half2_rn(v0, v1);
    __half2 h1 = __floats2half2_rn(v2, v3);
    ph[jt][0] = *(unsigned*)&h0;
    ph[jt][1] = *(unsigned*)&h1;
  }
  rs0 += __shfl_xor_sync(0xffffffffu, rs0, 1);
  rs0 += __shfl_xor_sync(0xffffffffu, rs0, 2);
  rs1 += __shfl_xor_sync(0xffffffffu, rs1, 1);
  rs1 += __shfl_xor_sync(0xffffffffu, rs1, 2);

  // PV gemm: O +/- = P @ V
#pragma unroll
  for (int kt = 0; kt < 4; kt++) {
    if (kt < jpmax) {
      unsigned a0 = ph[2 * kt][0], a1 = ph[2 * kt][1];
      unsigned a2 = ph[2 * kt + 1][0], a3 = ph[2 * kt + 1][1];
#pragma unroll
      for (int jp = 0; jp < 4; jp++) {
        unsigned b0, b1, b2, b3;
        ldsm4t(b0, b1, b2, b3, bVbase + (unsigned)(kt * 4096 + (((nh * 8 + 2 * jp + cb3) ^ l7) << 4)));
        mma16816(o[2 * jp],     a0, a1, a2, a3, b0, b1);
        mma16816(o[2 * jp + 1], a0, a1, a2, a3, b2, b3);
      }
    }
  }

  // epilogue
  float inv0 = 1.f / fmaxf(s_den[m0 + g]     + rs0, EPS_);
  float inv1 = 1.f / fmaxf(s_den[m0 + g + 8] + rs1, EPS_);
  float* op = out + qoff;
#pragma unroll
  for (int jt = 0; jt < 8; jt++) {
    int n0 = nh * 64 + jt * 8 + 2 * t4;
    float2 v0; v0.x = o[jt][0] * inv0; v0.y = o[jt][1] * inv0;
    float2 v1; v1.x = o[jt][2] * inv1; v1.y = o[jt][3] * inv1;
    *(float2*)(op + (m0 + g) * D_ + n0)     = v0;
    *(float2*)(op + (m0 + g + 8) * D_ + n0) = v1;
  }
}

// ---------------------------------------------------------------------------
#define P1_SMEM 115200
#define P3_SMEM 114944

extern "C" void kernel_launch(void* const* d_in, const int* in_sizes, int n_in,
                              void* d_out, int out_size) {
  (void)in_sizes; (void)n_in; (void)out_size;
  const float* q  = (const float*)d_in[0];
  const float* k  = (const float*)d_in[1];
  const float* v  = (const float*)d_in[2];
  const float* sc = (const float*)d_in[3];
  const float* bi = (const float*)d_in[4];
  float* out = (float*)d_out;

  static bool attrs_set = false;
  if (!attrs_set) {
    cudaFuncSetAttribute(la_pass1, cudaFuncAttributeMaxDynamicSharedMemorySize, P1_SMEM);
    cudaFuncSetAttribute(la_pass3, cudaFuncAttributeMaxDynamicSharedMemorySize, P3_SMEM);
    attrs_set = true;
  }

  la_pass1<<<dim3(NC_, BH_), 256, P1_SMEM>>>(k, v, sc, bi);
  la_pass2<<<(BH_ * D_ * D_ / 8) / 256, 256>>>();
  la_pass3<<<dim3(2 * NC_, BH_), 256, P3_SMEM>>>(q, k, v, sc, bi, out);
}